// round 1
// baseline (speedup 1.0000x reference)
#include <cuda_runtime.h>
#include <cuda_bf16.h>

// Problem constants (fixed shapes)
#define Bn 32
#define Sn 1024
#define Hn 1024
#define Wn 128
#define Kn 6
#define NH 16
#define HD 64
#define MROWS (Bn * Wn * Kn)   // 24576
#define NCOLS (2 * Hn)         // 2048

// Scratch for qk projection output: 24576 x 2048 f32 = ~201 MB
__device__ float g_qk[(size_t)MROWS * NCOLS];

// ---------------------------------------------------------------------------
// Kernel A: gathered sgemm  qk[r][c] = sum_h x[r][h] * W[c][h] + bias[c]
// where x[r] = mask ? TE[b, idx[r]] : 0
// 128x128 tile, BK=8, 256 threads, 8x8 per-thread microtile.
// ---------------------------------------------------------------------------
__global__ __launch_bounds__(256, 2) void gemm_qk_kernel(
    const float* __restrict__ TE,
    const float* __restrict__ Wt,
    const float* __restrict__ bias,
    const int* __restrict__ idx)
{
    __shared__ float As[8][128];
    __shared__ float Bs[8][128];
    __shared__ long long srcOff[128];

    const int tid = threadIdx.x;
    const int rowBase = blockIdx.y * 128;
    const int colBase = blockIdx.x * 128;

    if (tid < 128) {
        int r = rowBase + tid;
        int b = r / (Wn * Kn);
        int rem = r % (Wn * Kn);
        int kk = rem % Kn;
        int iv = idx[r];
        bool m = (kk == 0) || (iv != 0);
        srcOff[tid] = m ? ((long long)(b * Sn + iv) * Hn) : -1LL;
    }
    __syncthreads();

    const int ty = tid >> 4;   // 0..15
    const int tx = tid & 15;   // 0..15

    float acc[8][8];
#pragma unroll
    for (int i = 0; i < 8; i++)
#pragma unroll
        for (int j = 0; j < 8; j++) acc[i][j] = 0.f;

    const int aRow = tid >> 1;
    const int aCol = (tid & 1) * 4;
    const int bCol = tid >> 1;
    const int bH = (tid & 1) * 4;

    const long long mySrc = srcOff[aRow];
    const float* bSrcBase = Wt + (size_t)(colBase + bCol) * Hn + bH;

    for (int k0 = 0; k0 < Hn; k0 += 8) {
        // Load A tile (gathered)
        float4 av = make_float4(0.f, 0.f, 0.f, 0.f);
        if (mySrc >= 0) av = *(const float4*)(TE + mySrc + k0 + aCol);
        As[aCol + 0][aRow] = av.x;
        As[aCol + 1][aRow] = av.y;
        As[aCol + 2][aRow] = av.z;
        As[aCol + 3][aRow] = av.w;

        // Load B tile
        float4 bv = *(const float4*)(bSrcBase + k0);
        Bs[bH + 0][bCol] = bv.x;
        Bs[bH + 1][bCol] = bv.y;
        Bs[bH + 2][bCol] = bv.z;
        Bs[bH + 3][bCol] = bv.w;

        __syncthreads();

#pragma unroll
        for (int kk = 0; kk < 8; kk++) {
            float ra[8], rb[8];
            float4 a0 = *(const float4*)&As[kk][ty * 8];
            float4 a1 = *(const float4*)&As[kk][ty * 8 + 4];
            ra[0] = a0.x; ra[1] = a0.y; ra[2] = a0.z; ra[3] = a0.w;
            ra[4] = a1.x; ra[5] = a1.y; ra[6] = a1.z; ra[7] = a1.w;
            float4 b0 = *(const float4*)&Bs[kk][tx * 8];
            float4 b1 = *(const float4*)&Bs[kk][tx * 8 + 4];
            rb[0] = b0.x; rb[1] = b0.y; rb[2] = b0.z; rb[3] = b0.w;
            rb[4] = b1.x; rb[5] = b1.y; rb[6] = b1.z; rb[7] = b1.w;
#pragma unroll
            for (int i = 0; i < 8; i++)
#pragma unroll
                for (int j = 0; j < 8; j++)
                    acc[i][j] += ra[i] * rb[j];
        }
        __syncthreads();
    }

    // Epilogue: add bias, store
#pragma unroll
    for (int i = 0; i < 8; i++) {
        int m = rowBase + ty * 8 + i;
        float* outp = g_qk + (size_t)m * NCOLS + colBase + tx * 8;
        const float* bp = bias + colBase + tx * 8;
#pragma unroll
        for (int j = 0; j < 8; j += 4) {
            float4 v;
            v.x = acc[i][j + 0] + bp[j + 0];
            v.y = acc[i][j + 1] + bp[j + 1];
            v.z = acc[i][j + 2] + bp[j + 2];
            v.w = acc[i][j + 3] + bp[j + 3];
            *(float4*)(outp + j) = v;
        }
    }
}

// ---------------------------------------------------------------------------
// Kernel B: copy token_embeddings -> out, zeroing all masked subtoken rows.
// One float4 per thread.
// ---------------------------------------------------------------------------
__global__ __launch_bounds__(256) void copy_zero_kernel(
    const float* __restrict__ TE,
    const int* __restrict__ idx,
    float* __restrict__ out)
{
    size_t gid = (size_t)blockIdx.x * 256 + threadIdx.x;  // float4 index
    int row = (int)(gid >> 8);        // H/4 = 256 float4 per row
    int b = row >> 10;                // / S
    int s = row & 1023;
    int w = s >> 3;
    int kk = s & 7;
    bool zero = false;
    if (kk < Kn) {
        int iv = idx[(b * Wn + w) * Kn + kk];
        zero = (kk == 0) || (iv != 0);
    }
    float4 v;
    if (zero) {
        v = make_float4(0.f, 0.f, 0.f, 0.f);
    } else {
        v = ((const float4*)TE)[gid];
    }
    ((float4*)out)[gid] = v;
}

// ---------------------------------------------------------------------------
// Kernel C: per-window attention -> contrib -> unified, scatter to out.
// One CTA (256 threads) per window.
// ---------------------------------------------------------------------------
struct SmemB {
    float qk[Kn][NCOLS];      // 6 x 2048 = 48 KB
    float sc[NH][Kn][Kn];     // scores / attn
    float wm[Kn][Kn];
    float contrib[8];
    float smask[8];
    int sidx[8];
    float sinv;
};

__global__ __launch_bounds__(256) void attn_merge_kernel(
    const float* __restrict__ TE,
    const int* __restrict__ idx,
    float* __restrict__ out)
{
    extern __shared__ unsigned char smraw[];
    SmemB* sm = reinterpret_cast<SmemB*>(smraw);

    const int tid = threadIdx.x;
    const int wg = blockIdx.x;     // 0..4095 window id = b*W + w
    const int b = wg >> 7;

    if (tid < Kn) {
        int iv = idx[wg * Kn + tid];
        sm->sidx[tid] = iv;
        sm->smask[tid] = (tid == 0 || iv != 0) ? 1.f : 0.f;
    }

    // Load 6 x 2048 qk rows into smem
    const float4* src = (const float4*)(g_qk + (size_t)wg * Kn * NCOLS);
    float4* dst = (float4*)sm->qk;
#pragma unroll
    for (int i = 0; i < (Kn * NCOLS / 4) / 256; i++)
        dst[tid + i * 256] = src[tid + i * 256];
    __syncthreads();

    // Scores: 16 heads x 6 x 6 = 576 dot(64) tasks
    for (int t = tid; t < NH * Kn * Kn; t += 256) {
        int n = t / (Kn * Kn);
        int ij = t % (Kn * Kn);
        int i = ij / Kn, j = ij % Kn;
        const float* qp = &sm->qk[i][n * HD];
        const float* kp = &sm->qk[j][Hn + n * HD];
        float d = 0.f;
#pragma unroll
        for (int dd = 0; dd < HD; dd++) d += qp[dd] * kp[dd];
        sm->sc[n][i][j] = d * 0.125f + sm->smask[i] * sm->smask[j];
    }
    __syncthreads();

    // Softmax per (head, row)
    if (tid < NH * Kn) {
        int n = tid / Kn, i = tid % Kn;
        float* row = sm->sc[n][i];
        float mx = row[0];
#pragma unroll
        for (int j = 1; j < Kn; j++) mx = fmaxf(mx, row[j]);
        float e[Kn];
        float s = 0.f;
#pragma unroll
        for (int j = 0; j < Kn; j++) { e[j] = __expf(row[j] - mx); s += e[j]; }
        float inv = 1.f / s;
#pragma unroll
        for (int j = 0; j < Kn; j++) row[j] = e[j] * inv;
    }
    __syncthreads();

    // Mean over heads
    if (tid < Kn * Kn) {
        int i = tid / Kn, j = tid % Kn;
        float s = 0.f;
#pragma unroll
        for (int n = 0; n < NH; n++) s += sm->sc[n][i][j];
        sm->wm[i][j] = s * (1.f / NH);
    }
    __syncthreads();

    // contrib[j] = sum_i pair(i,j) * wm[i][j]
    if (tid < Kn) {
        int j = tid;
        float c = 0.f;
#pragma unroll
        for (int i = 0; i < Kn; i++)
            c += sm->smask[i] * sm->smask[j] * sm->wm[i][j];
        sm->contrib[j] = c;
    }
    __syncthreads();
    if (tid == 0) {
        float s = 0.f;
#pragma unroll
        for (int j = 0; j < Kn; j++) s += sm->contrib[j];
        sm->sinv = 1.f / (s + 1e-8f);
    }
    __syncthreads();

    // unified[h] = sum_k contrib_norm[k] * TE[b, sidx[k], h]; write at row sidx[0]
    float c[Kn];
    float inv = sm->sinv;
#pragma unroll
    for (int kk = 0; kk < Kn; kk++) c[kk] = sm->contrib[kk] * inv;

    const float4* rows[Kn];
#pragma unroll
    for (int kk = 0; kk < Kn; kk++)
        rows[kk] = (const float4*)(TE + ((size_t)b * Sn + sm->sidx[kk]) * Hn);

    float4* orow = (float4*)(out + ((size_t)b * Sn + sm->sidx[0]) * Hn);
    // 1024 floats = 256 float4: exactly one per thread
    {
        float4 a = make_float4(0.f, 0.f, 0.f, 0.f);
#pragma unroll
        for (int kk = 0; kk < Kn; kk++) {
            float4 v = rows[kk][tid];
            a.x += c[kk] * v.x;
            a.y += c[kk] * v.y;
            a.z += c[kk] * v.z;
            a.w += c[kk] * v.w;
        }
        orow[tid] = a;
    }
}

// ---------------------------------------------------------------------------
extern "C" void kernel_launch(void* const* d_in, const int* in_sizes, int n_in,
                              void* d_out, int out_size)
{
    const float* TE   = (const float*)d_in[0];   // (32,1024,1024) f32
    const float* Wt   = (const float*)d_in[1];   // (3072,1024) f32
    const float* bias = (const float*)d_in[2];   // (3072,) f32
    const int* idx    = (const int*)d_in[3];     // (32,128,6) i32
    float* out = (float*)d_out;

    // Kernel A: projection GEMM into g_qk
    {
        dim3 grid(NCOLS / 128, MROWS / 128);   // (16, 192)
        gemm_qk_kernel<<<grid, 256>>>(TE, Wt, bias, idx);
    }

    // Kernel B: copy + zero
    {
        size_t total4 = (size_t)Bn * Sn * Hn / 4;   // 8388608
        copy_zero_kernel<<<(unsigned)(total4 / 256), 256>>>(TE, idx, out);
    }

    // Kernel C: attention + unified scatter (needs out already written)
    {
        static bool attr_set = false;
        if (!attr_set) {
            cudaFuncSetAttribute(attn_merge_kernel,
                                 cudaFuncAttributeMaxDynamicSharedMemorySize,
                                 (int)sizeof(SmemB));
            attr_set = true;
        }
        attn_merge_kernel<<<Bn * Wn, 256, sizeof(SmemB)>>>(TE, idx, out);
    }
}

// round 2
// speedup vs baseline: 2.6872x; 2.6872x over previous
#include <cuda_runtime.h>
#include <cuda_bf16.h>
#include <cstdint>

// Problem constants (fixed shapes)
#define Bn 32
#define Sn 1024
#define Hn 1024
#define Wn 128
#define Kn 6
#define NH 16
#define HD 64
#define MROWS (Bn * Wn * Kn)   // 24576
#define NCOLS (2 * Hn)         // 2048

// Scratch for qk projection output: 24576 x 2048 f32 = ~201 MB
__device__ float g_qk[(size_t)MROWS * NCOLS];

__device__ __forceinline__ uint32_t f2tf32(float x) {
    uint32_t u;
    asm("cvt.rna.tf32.f32 %0, %1;" : "=r"(u) : "f"(x));
    return u;
}

__device__ __forceinline__ void mma_tf32(float& c0, float& c1, float& c2, float& c3,
                                         uint32_t a0, uint32_t a1, uint32_t a2, uint32_t a3,
                                         uint32_t b0, uint32_t b1)
{
    asm volatile(
        "mma.sync.aligned.m16n8k8.row.col.f32.tf32.tf32.f32 "
        "{%0,%1,%2,%3},{%4,%5,%6,%7},{%8,%9},{%0,%1,%2,%3};"
        : "+f"(c0), "+f"(c1), "+f"(c2), "+f"(c3)
        : "r"(a0), "r"(a1), "r"(a2), "r"(a3), "r"(b0), "r"(b1));
}

// ---------------------------------------------------------------------------
// Kernel A: gathered TF32 tensor-core GEMM
//   qk[r][c] = sum_h x[r][h] * Wt[c][h] + bias[c],  x[r] = mask ? TE[b,idx[r]] : 0
// 128x128 tile, BK=16, 256 threads (8 warps, 4x2), warp tile 32x64 via
// mma.m16n8k8 tf32. Fragment-order smem staging with XOR bank swizzle.
// ---------------------------------------------------------------------------
__global__ __launch_bounds__(256) void gemm_qk_tc(
    const float* __restrict__ TE,
    const float* __restrict__ Wt,
    const float* __restrict__ bias,
    const int* __restrict__ idx)
{
    __shared__ uint32_t AsU[2][2048];   // 2 stages x 8KB (frag layout, swizzled)
    __shared__ uint32_t BsU[2][2048];
    __shared__ long long srcOff[128];
    __shared__ float biasSm[128];

    const int tid = threadIdx.x;
    const int rowBase = blockIdx.y * 128;
    const int colBase = blockIdx.x * 128;

    if (tid < 128) {
        int r = rowBase + tid;
        int b = r / (Wn * Kn);
        int kk = r % Kn;                 // (Wn*Kn) % Kn == 0, so r % Kn is the k slot
        int iv = idx[r];
        bool m = (kk == 0) || (iv != 0);
        srcOff[tid] = m ? ((long long)(b * Sn + iv) * Hn) : -1LL;
        biasSm[tid] = bias[colBase + tid];
    }
    __syncthreads();

    // ---- loader mapping: thread t -> row lrow = t>>1, k-half halfk = t&1 ----
    const int lrow = tid >> 1;
    const int halfk = tid & 1;

    // A writer constants (row -> frag coords)
    const int gA  = lrow & 7;
    const int hiA = (lrow >> 3) & 1;
    const int mtA = lrow >> 4;
    const int gxA = (gA >> 1) & 3;                    // XOR swizzle for A
    const int aWBase = (mtA * 2 + halfk) * 128 + 16 * gA + hiA;

    // B writer constants (n = lrow)
    const int gB  = lrow & 7;
    const int ntB = lrow >> 3;
    const int swB = (lrow >> 2) & 3;                  // XOR swizzle for B
    const int bWBase = (ntB * 2 + halfk) * 64 + 8 * gB;

    const long long myOff = srcOff[lrow];
    const float* aSrcBase = (myOff >= 0) ? (TE + myOff + halfk * 8) : nullptr;
    const float* bSrcBase = Wt + (size_t)(colBase + lrow) * Hn + halfk * 8;

    // ---- compute mapping ----
    const int wid = tid >> 5, lane = tid & 31;
    const int wr = wid >> 1, wc = wid & 1;            // 4 x 2 warp grid
    const int g4 = lane >> 2, t4 = lane & 3;
    const int aROff = 16 * g4 + 4 * (t4 ^ ((g4 >> 1) & 3));
    const int g2 = g4 >> 2;

    float acc[2][8][4];
#pragma unroll
    for (int mi = 0; mi < 2; mi++)
#pragma unroll
        for (int ni = 0; ni < 8; ni++)
#pragma unroll
            for (int q = 0; q < 4; q++) acc[mi][ni][q] = 0.f;

    float4 ra0, ra1, rb0, rb1;

    // prologue: load + store stage 0
    {
        if (aSrcBase) {
            ra0 = *(const float4*)(aSrcBase + 0);
            ra1 = *(const float4*)(aSrcBase + 4);
        } else {
            ra0 = make_float4(0.f, 0.f, 0.f, 0.f);
            ra1 = ra0;
        }
        rb0 = *(const float4*)(bSrcBase + 0);
        rb1 = *(const float4*)(bSrcBase + 4);

        uint32_t* A = AsU[0];
        uint32_t* B = BsU[0];
        float va[8] = {ra0.x, ra0.y, ra0.z, ra0.w, ra1.x, ra1.y, ra1.z, ra1.w};
        float vb[8] = {rb0.x, rb0.y, rb0.z, rb0.w, rb1.x, rb1.y, rb1.z, rb1.w};
#pragma unroll
        for (int c = 0; c < 2; c++)
#pragma unroll
            for (int j = 0; j < 4; j++) {
                A[aWBase + 4 * (j ^ gxA) + 2 * c] = f2tf32(va[c * 4 + j]);
                B[bWBase + 2 * (j ^ swB) + c]     = f2tf32(vb[c * 4 + j]);
            }
    }
    __syncthreads();

    for (int it = 0; it < 64; ++it) {
        // prefetch next stage into registers
        if (it + 1 < 64) {
            int kG = (it + 1) * 16;
            if (aSrcBase) {
                ra0 = *(const float4*)(aSrcBase + kG);
                ra1 = *(const float4*)(aSrcBase + kG + 4);
            } else {
                ra0 = make_float4(0.f, 0.f, 0.f, 0.f);
                ra1 = ra0;
            }
            rb0 = *(const float4*)(bSrcBase + kG);
            rb1 = *(const float4*)(bSrcBase + kG + 4);
        }

        // compute on current stage
        const uint32_t* A = AsU[it & 1];
        const uint32_t* B = BsU[it & 1];
#pragma unroll
        for (int ks = 0; ks < 2; ks++) {
            uint4 af[2];
#pragma unroll
            for (int mi = 0; mi < 2; mi++)
                af[mi] = *(const uint4*)&A[((wr * 2 + mi) * 2 + ks) * 128 + aROff];

            uint32_t bf[8][2];
#pragma unroll
            for (int ni = 0; ni < 8; ni++) {
                int nt = wc * 8 + ni;
                int sw = (2 * nt + g2) & 3;
                uint2 bv = *(const uint2*)&B[(nt * 2 + ks) * 64 + 8 * g4 + 2 * (t4 ^ sw)];
                bf[ni][0] = bv.x;
                bf[ni][1] = bv.y;
            }
#pragma unroll
            for (int mi = 0; mi < 2; mi++)
#pragma unroll
                for (int ni = 0; ni < 8; ni++)
                    mma_tf32(acc[mi][ni][0], acc[mi][ni][1], acc[mi][ni][2], acc[mi][ni][3],
                             af[mi].x, af[mi].y, af[mi].z, af[mi].w,
                             bf[ni][0], bf[ni][1]);
        }

        // store next stage
        if (it + 1 < 64) {
            uint32_t* An = AsU[(it + 1) & 1];
            uint32_t* Bs = BsU[(it + 1) & 1];
            float va[8] = {ra0.x, ra0.y, ra0.z, ra0.w, ra1.x, ra1.y, ra1.z, ra1.w};
            float vb[8] = {rb0.x, rb0.y, rb0.z, rb0.w, rb1.x, rb1.y, rb1.z, rb1.w};
#pragma unroll
            for (int c = 0; c < 2; c++)
#pragma unroll
                for (int j = 0; j < 4; j++) {
                    An[aWBase + 4 * (j ^ gxA) + 2 * c] = f2tf32(va[c * 4 + j]);
                    Bs[bWBase + 2 * (j ^ swB) + c]     = f2tf32(vb[c * 4 + j]);
                }
        }
        __syncthreads();
    }

    // epilogue: add bias, store to g_qk
#pragma unroll
    for (int mi = 0; mi < 2; mi++) {
        int row0 = rowBase + wr * 32 + mi * 16 + g4;
#pragma unroll
        for (int ni = 0; ni < 8; ni++) {
            int cl = wc * 64 + ni * 8 + t4 * 2;
            float b0 = biasSm[cl], b1 = biasSm[cl + 1];
            float2 v0 = make_float2(acc[mi][ni][0] + b0, acc[mi][ni][1] + b1);
            float2 v1 = make_float2(acc[mi][ni][2] + b0, acc[mi][ni][3] + b1);
            *(float2*)&g_qk[(size_t)row0 * NCOLS + colBase + cl] = v0;
            *(float2*)&g_qk[(size_t)(row0 + 8) * NCOLS + colBase + cl] = v1;
        }
    }
}

// ---------------------------------------------------------------------------
// Kernel B: copy token_embeddings -> out, zeroing all masked subtoken rows.
// ---------------------------------------------------------------------------
__global__ __launch_bounds__(256) void copy_zero_kernel(
    const float* __restrict__ TE,
    const int* __restrict__ idx,
    float* __restrict__ out)
{
    size_t gid = (size_t)blockIdx.x * 256 + threadIdx.x;  // float4 index
    int row = (int)(gid >> 8);        // H/4 = 256 float4 per row
    int b = row >> 10;                // / S
    int s = row & 1023;
    int w = s >> 3;
    int kk = s & 7;
    bool zero = false;
    if (kk < Kn) {
        int iv = idx[(b * Wn + w) * Kn + kk];
        zero = (kk == 0) || (iv != 0);
    }
    float4 v;
    if (zero) {
        v = make_float4(0.f, 0.f, 0.f, 0.f);
    } else {
        v = ((const float4*)TE)[gid];
    }
    ((float4*)out)[gid] = v;
}

// ---------------------------------------------------------------------------
// Kernel C: per-window attention -> contrib -> unified, scatter to out.
// ---------------------------------------------------------------------------
struct SmemB {
    float qk[Kn][NCOLS];      // 6 x 2048 = 48 KB
    float sc[NH][Kn][Kn];
    float wm[Kn][Kn];
    float contrib[8];
    float smask[8];
    int sidx[8];
    float sinv;
};

__global__ __launch_bounds__(256) void attn_merge_kernel(
    const float* __restrict__ TE,
    const int* __restrict__ idx,
    float* __restrict__ out)
{
    extern __shared__ unsigned char smraw[];
    SmemB* sm = reinterpret_cast<SmemB*>(smraw);

    const int tid = threadIdx.x;
    const int wg = blockIdx.x;     // window id = b*W + w
    const int b = wg >> 7;

    if (tid < Kn) {
        int iv = idx[wg * Kn + tid];
        sm->sidx[tid] = iv;
        sm->smask[tid] = (tid == 0 || iv != 0) ? 1.f : 0.f;
    }

    const float4* src = (const float4*)(g_qk + (size_t)wg * Kn * NCOLS);
    float4* dst = (float4*)sm->qk;
#pragma unroll
    for (int i = 0; i < (Kn * NCOLS / 4) / 256; i++)
        dst[tid + i * 256] = src[tid + i * 256];
    __syncthreads();

    for (int t = tid; t < NH * Kn * Kn; t += 256) {
        int n = t / (Kn * Kn);
        int ij = t % (Kn * Kn);
        int i = ij / Kn, j = ij % Kn;
        const float* qp = &sm->qk[i][n * HD];
        const float* kp = &sm->qk[j][Hn + n * HD];
        float d = 0.f;
#pragma unroll
        for (int dd = 0; dd < HD; dd++) d += qp[dd] * kp[dd];
        sm->sc[n][i][j] = d * 0.125f + sm->smask[i] * sm->smask[j];
    }
    __syncthreads();

    if (tid < NH * Kn) {
        int n = tid / Kn, i = tid % Kn;
        float* row = sm->sc[n][i];
        float mx = row[0];
#pragma unroll
        for (int j = 1; j < Kn; j++) mx = fmaxf(mx, row[j]);
        float e[Kn];
        float s = 0.f;
#pragma unroll
        for (int j = 0; j < Kn; j++) { e[j] = __expf(row[j] - mx); s += e[j]; }
        float inv = 1.f / s;
#pragma unroll
        for (int j = 0; j < Kn; j++) row[j] = e[j] * inv;
    }
    __syncthreads();

    if (tid < Kn * Kn) {
        int i = tid / Kn, j = tid % Kn;
        float s = 0.f;
#pragma unroll
        for (int n = 0; n < NH; n++) s += sm->sc[n][i][j];
        sm->wm[i][j] = s * (1.f / NH);
    }
    __syncthreads();

    if (tid < Kn) {
        int j = tid;
        float c = 0.f;
#pragma unroll
        for (int i = 0; i < Kn; i++)
            c += sm->smask[i] * sm->smask[j] * sm->wm[i][j];
        sm->contrib[j] = c;
    }
    __syncthreads();
    if (tid == 0) {
        float s = 0.f;
#pragma unroll
        for (int j = 0; j < Kn; j++) s += sm->contrib[j];
        sm->sinv = 1.f / (s + 1e-8f);
    }
    __syncthreads();

    float c[Kn];
    float inv = sm->sinv;
#pragma unroll
    for (int kk = 0; kk < Kn; kk++) c[kk] = sm->contrib[kk] * inv;

    const float4* rows[Kn];
#pragma unroll
    for (int kk = 0; kk < Kn; kk++)
        rows[kk] = (const float4*)(TE + ((size_t)b * Sn + sm->sidx[kk]) * Hn);

    float4* orow = (float4*)(out + ((size_t)b * Sn + sm->sidx[0]) * Hn);
    {
        float4 a = make_float4(0.f, 0.f, 0.f, 0.f);
#pragma unroll
        for (int kk = 0; kk < Kn; kk++) {
            float4 v = rows[kk][tid];
            a.x += c[kk] * v.x;
            a.y += c[kk] * v.y;
            a.z += c[kk] * v.z;
            a.w += c[kk] * v.w;
        }
        orow[tid] = a;
    }
}

// ---------------------------------------------------------------------------
extern "C" void kernel_launch(void* const* d_in, const int* in_sizes, int n_in,
                              void* d_out, int out_size)
{
    const float* TE   = (const float*)d_in[0];   // (32,1024,1024) f32
    const float* Wt   = (const float*)d_in[1];   // (3072,1024) f32
    const float* bias = (const float*)d_in[2];   // (3072,) f32
    const int* idx    = (const int*)d_in[3];     // (32,128,6) i32
    float* out = (float*)d_out;

    // Kernel A: TF32 tensor-core projection GEMM into g_qk
    {
        dim3 grid(NCOLS / 128, MROWS / 128);   // (16, 192)
        gemm_qk_tc<<<grid, 256>>>(TE, Wt, bias, idx);
    }

    // Kernel B: copy + zero
    {
        size_t total4 = (size_t)Bn * Sn * Hn / 4;
        copy_zero_kernel<<<(unsigned)(total4 / 256), 256>>>(TE, idx, out);
    }

    // Kernel C: attention + unified scatter (needs out already written)
    {
        static bool attr_set = false;
        if (!attr_set) {
            cudaFuncSetAttribute(attn_merge_kernel,
                                 cudaFuncAttributeMaxDynamicSharedMemorySize,
                                 (int)sizeof(SmemB));
            attr_set = true;
        }
        attn_merge_kernel<<<Bn * Wn, 256, sizeof(SmemB)>>>(TE, idx, out);
    }
}

// round 4
// speedup vs baseline: 3.0157x; 1.1222x over previous
#include <cuda_runtime.h>
#include <cuda_bf16.h>
#include <cstdint>

// Problem constants (fixed shapes)
#define Bn 32
#define Sn 1024
#define Hn 1024
#define Wn 128
#define Kn 6
#define NH 16
#define HD 64
#define MROWS (Bn * Wn * Kn)   // 24576
#define NCOLS (2 * Hn)         // 2048

// Scratch for qk projection output: 24576 x 2048 f32 = ~201 MB
__device__ float g_qk[(size_t)MROWS * NCOLS];

__device__ __forceinline__ uint32_t smem_u32(const void* p) {
    uint32_t a;
    asm("{ .reg .u64 t; cvta.to.shared.u64 t, %1; cvt.u32.u64 %0, t; }" : "=r"(a) : "l"(p));
    return a;
}
__device__ __forceinline__ void mma_tf32(float& c0, float& c1, float& c2, float& c3,
                                         uint32_t a0, uint32_t a1, uint32_t a2, uint32_t a3,
                                         uint32_t b0, uint32_t b1)
{
    asm volatile(
        "mma.sync.aligned.m16n8k8.row.col.f32.tf32.tf32.f32 "
        "{%0,%1,%2,%3},{%4,%5,%6,%7},{%8,%9},{%0,%1,%2,%3};"
        : "+f"(c0), "+f"(c1), "+f"(c2), "+f"(c3)
        : "r"(a0), "r"(a1), "r"(a2), "r"(a3), "r"(b0), "r"(b1));
}
__device__ __forceinline__ void cpasync16(uint32_t dst, const float* src, uint32_t sz) {
    asm volatile("cp.async.cg.shared.global [%0], [%1], 16, %2;"
                 :: "r"(dst), "l"(src), "r"(sz) : "memory");
}
#define CP_COMMIT() asm volatile("cp.async.commit_group;" ::: "memory")
#define CP_WAIT(n)  asm volatile("cp.async.wait_group %0;" :: "n"(n) : "memory")
#define SW128(o) ((o) ^ (((o) >> 3) & 0x70))

// ---------------------------------------------------------------------------
// Kernel A: gathered TF32 tensor-core GEMM with cp.async pipeline.
//   qk[r][c] = sum_h x[r][h] * Wt[c][h] + bias[c],  x[r] = mask ? TE[b,idx[r]] : 0
// Tile 128x128, BK=16, 4 stages, 256 threads (8 warps 4x2), warp tile 32x64.
// SMEM: [0:1024) srcOff, [1024:1536) bias, [2048 + s*16KB) stages (A 8KB | B 8KB)
// ---------------------------------------------------------------------------
#define STAGE_BYTES 16384
#define GEMM_SMEM (2048 + 4 * STAGE_BYTES)

__global__ __launch_bounds__(256, 2) void gemm_qk_cp(
    const float* __restrict__ TE,
    const float* __restrict__ Wt,
    const float* __restrict__ bias,
    const int* __restrict__ idx)
{
    extern __shared__ unsigned char sm[];
    long long* srcOff = (long long*)sm;
    float* biasSm = (float*)(sm + 1024);
    const uint32_t smBase = smem_u32(sm);

    const int tid = threadIdx.x;
    const int rowBase = blockIdx.y * 128;
    const int colBase = blockIdx.x * 128;

    if (tid < 128) {
        int r = rowBase + tid;
        int b = r / (Wn * Kn);
        int kk = r % Kn;                 // (Wn*Kn) % Kn == 0
        int iv = idx[r];
        bool m = (kk == 0) || (iv != 0);
        srcOff[tid] = m ? ((long long)(b * Sn + iv) * Hn) : -1LL;
        biasSm[tid] = bias[colBase + tid];
    }
    __syncthreads();

    // ---- loader mapping: thread t -> row t>>1, k-half t&1 (8 floats) ----
    const int lrow = tid >> 1;
    const int lhalf = tid & 1;
    const long long aOff = srcOff[lrow];
    const float* aSrc = TE + (aOff >= 0 ? aOff : 0) + lhalf * 8;
    const uint32_t aSz = (aOff >= 0) ? 16u : 0u;
    const float* bSrc = Wt + (size_t)(colBase + lrow) * Hn + lhalf * 8;

    const uint32_t dOff = (uint32_t)(lrow * 64 + lhalf * 32);
    const uint32_t aD0 = smBase + 2048 + SW128(dOff);
    const uint32_t aD1 = smBase + 2048 + SW128(dOff + 16);
    const uint32_t bD0 = aD0 + 8192;
    const uint32_t bD1 = aD1 + 8192;

    // ---- compute mapping ----
    const int wid = tid >> 5, lane = tid & 31;
    const int wr = wid >> 1, wc = wid & 1;            // 4 x 2 warp grid
    const int g4 = lane >> 2, t4 = lane & 3;
    const uint32_t ax0 = (uint32_t)((g4 >> 1) << 4);  // swizzle XOR, rows r & r+16
    const uint32_t ax1 = ax0 ^ 0x40u;                 // rows r+8

    float acc[2][8][4];
#pragma unroll
    for (int mi = 0; mi < 2; mi++)
#pragma unroll
        for (int ni = 0; ni < 8; ni++)
#pragma unroll
            for (int q = 0; q < 4; q++) acc[mi][ni][q] = 0.f;

    // ---- prologue: prefetch stages 0..2 ----
#pragma unroll
    for (int s = 0; s < 3; s++) {
        const uint32_t sb = (uint32_t)(s * STAGE_BYTES);
        const int k0 = s * 16;
        cpasync16(aD0 + sb, aSrc + k0, aSz);
        cpasync16(aD1 + sb, aSrc + k0 + 4, aSz);
        cpasync16(bD0 + sb, bSrc + k0, 16u);
        cpasync16(bD1 + sb, bSrc + k0 + 4, 16u);
        CP_COMMIT();
    }

    // ---- mainloop: 64 iterations of BK=16 ----
    for (int it = 0; it < 64; ++it) {
        CP_WAIT(2);
        __syncthreads();

        // issue loads for stage it+3 (reuses buffer of it-1; all warps synced)
        if (it + 3 < 64) {
            const uint32_t sb = (uint32_t)(((it + 3) & 3) * STAGE_BYTES);
            const int k0 = (it + 3) * 16;
            cpasync16(aD0 + sb, aSrc + k0, aSz);
            cpasync16(aD1 + sb, aSrc + k0 + 4, aSz);
            cpasync16(bD0 + sb, bSrc + k0, 16u);
            cpasync16(bD1 + sb, bSrc + k0 + 4, 16u);
        }
        CP_COMMIT();

        // compute on stage it&3
        const unsigned char* sa = sm + 2048 + (it & 3) * STAGE_BYTES;
#pragma unroll
        for (int ks = 0; ks < 2; ks++) {
            uint32_t af[2][4];
#pragma unroll
            for (int mi = 0; mi < 2; mi++) {
                uint32_t b0 = (uint32_t)(wr * 2048 + mi * 1024 + ks * 32 + g4 * 64 + t4 * 4);
                af[mi][0] = *(const uint32_t*)(sa + ((b0)        ^ ax0));
                af[mi][2] = *(const uint32_t*)(sa + ((b0 + 16)   ^ ax0));
                af[mi][1] = *(const uint32_t*)(sa + ((b0 + 512)  ^ ax1));
                af[mi][3] = *(const uint32_t*)(sa + ((b0 + 528)  ^ ax1));
            }
#pragma unroll
            for (int ni = 0; ni < 8; ni++) {
                uint32_t bb = (uint32_t)(8192 + wc * 4096 + ni * 512 + ks * 32 + g4 * 64 + t4 * 4);
                uint32_t ax = (ni & 1) ? ax1 : ax0;
                uint32_t b0 = *(const uint32_t*)(sa + ((bb)      ^ ax));
                uint32_t b1 = *(const uint32_t*)(sa + ((bb + 16) ^ ax));
#pragma unroll
                for (int mi = 0; mi < 2; mi++)
                    mma_tf32(acc[mi][ni][0], acc[mi][ni][1], acc[mi][ni][2], acc[mi][ni][3],
                             af[mi][0], af[mi][1], af[mi][2], af[mi][3], b0, b1);
            }
        }
    }

    // ---- epilogue: add bias, store to g_qk ----
#pragma unroll
    for (int mi = 0; mi < 2; mi++) {
        int row0 = rowBase + wr * 32 + mi * 16 + g4;
#pragma unroll
        for (int ni = 0; ni < 8; ni++) {
            int cl = wc * 64 + ni * 8 + t4 * 2;
            float b0 = biasSm[cl], b1 = biasSm[cl + 1];
            float2 v0 = make_float2(acc[mi][ni][0] + b0, acc[mi][ni][1] + b1);
            float2 v1 = make_float2(acc[mi][ni][2] + b0, acc[mi][ni][3] + b1);
            *(float2*)&g_qk[(size_t)row0 * NCOLS + colBase + cl] = v0;
            *(float2*)&g_qk[(size_t)(row0 + 8) * NCOLS + colBase + cl] = v1;
        }
    }
}

// ---------------------------------------------------------------------------
// Kernel B: copy token_embeddings -> out, zeroing all masked subtoken rows.
// ---------------------------------------------------------------------------
__global__ __launch_bounds__(256) void copy_zero_kernel(
    const float* __restrict__ TE,
    const int* __restrict__ idx,
    float* __restrict__ out)
{
    size_t gid = (size_t)blockIdx.x * 256 + threadIdx.x;  // float4 index
    int row = (int)(gid >> 8);        // H/4 = 256 float4 per row
    int b = row >> 10;                // / S
    int s = row & 1023;
    int w = s >> 3;
    int kk = s & 7;
    bool zero = false;
    if (kk < Kn) {
        int iv = idx[(b * Wn + w) * Kn + kk];
        zero = (kk == 0) || (iv != 0);
    }
    float4 v;
    if (zero) {
        v = make_float4(0.f, 0.f, 0.f, 0.f);
    } else {
        v = ((const float4*)TE)[gid];
    }
    ((float4*)out)[gid] = v;
}

// ---------------------------------------------------------------------------
// Kernel C: per-window attention -> contrib -> unified, scatter to out.
// ---------------------------------------------------------------------------
struct SmemB {
    float qk[Kn][NCOLS];      // 6 x 2048 = 48 KB
    float sc[NH][Kn][Kn];
    float wm[Kn][Kn];
    float contrib[8];
    float smask[8];
    int sidx[8];
    float sinv;
};

__global__ __launch_bounds__(256) void attn_merge_kernel(
    const float* __restrict__ TE,
    const int* __restrict__ idx,
    float* __restrict__ out)
{
    extern __shared__ unsigned char smraw[];
    SmemB* sm = reinterpret_cast<SmemB*>(smraw);

    const int tid = threadIdx.x;
    const int wg = blockIdx.x;     // window id = b*W + w
    const int b = wg >> 7;

    if (tid < Kn) {
        int iv = idx[wg * Kn + tid];
        sm->sidx[tid] = iv;
        sm->smask[tid] = (tid == 0 || iv != 0) ? 1.f : 0.f;
    }

    const float4* src = (const float4*)(g_qk + (size_t)wg * Kn * NCOLS);
    float4* dst = (float4*)sm->qk;
#pragma unroll
    for (int i = 0; i < (Kn * NCOLS / 4) / 256; i++)
        dst[tid + i * 256] = src[tid + i * 256];
    __syncthreads();

    for (int t = tid; t < NH * Kn * Kn; t += 256) {
        int n = t / (Kn * Kn);
        int ij = t % (Kn * Kn);
        int i = ij / Kn, j = ij % Kn;
        const float* qp = &sm->qk[i][n * HD];
        const float* kp = &sm->qk[j][Hn + n * HD];
        float d = 0.f;
#pragma unroll
        for (int dd = 0; dd < HD; dd++) d += qp[dd] * kp[dd];
        sm->sc[n][i][j] = d * 0.125f + sm->smask[i] * sm->smask[j];
    }
    __syncthreads();

    if (tid < NH * Kn) {
        int n = tid / Kn, i = tid % Kn;
        float* row = sm->sc[n][i];
        float mx = row[0];
#pragma unroll
        for (int j = 1; j < Kn; j++) mx = fmaxf(mx, row[j]);
        float e[Kn];
        float s = 0.f;
#pragma unroll
        for (int j = 0; j < Kn; j++) { e[j] = __expf(row[j] - mx); s += e[j]; }
        float inv = 1.f / s;
#pragma unroll
        for (int j = 0; j < Kn; j++) row[j] = e[j] * inv;
    }
    __syncthreads();

    if (tid < Kn * Kn) {
        int i = tid / Kn, j = tid % Kn;
        float s = 0.f;
#pragma unroll
        for (int n = 0; n < NH; n++) s += sm->sc[n][i][j];
        sm->wm[i][j] = s * (1.f / NH);
    }
    __syncthreads();

    if (tid < Kn) {
        int j = tid;
        float c = 0.f;
#pragma unroll
        for (int i = 0; i < Kn; i++)
            c += sm->smask[i] * sm->smask[j] * sm->wm[i][j];
        sm->contrib[j] = c;
    }
    __syncthreads();
    if (tid == 0) {
        float s = 0.f;
#pragma unroll
        for (int j = 0; j < Kn; j++) s += sm->contrib[j];
        sm->sinv = 1.f / (s + 1e-8f);
    }
    __syncthreads();

    float c[Kn];
    float inv = sm->sinv;
#pragma unroll
    for (int kk = 0; kk < Kn; kk++) c[kk] = sm->contrib[kk] * inv;

    const float4* rows[Kn];
#pragma unroll
    for (int kk = 0; kk < Kn; kk++)
        rows[kk] = (const float4*)(TE + ((size_t)b * Sn + sm->sidx[kk]) * Hn);

    float4* orow = (float4*)(out + ((size_t)b * Sn + sm->sidx[0]) * Hn);
    {
        float4 a = make_float4(0.f, 0.f, 0.f, 0.f);
#pragma unroll
        for (int kk = 0; kk < Kn; kk++) {
            float4 v = rows[kk][tid];
            a.x += c[kk] * v.x;
            a.y += c[kk] * v.y;
            a.z += c[kk] * v.z;
            a.w += c[kk] * v.w;
        }
        orow[tid] = a;
    }
}

// ---------------------------------------------------------------------------
extern "C" void kernel_launch(void* const* d_in, const int* in_sizes, int n_in,
                              void* d_out, int out_size)
{
    const float* TE   = (const float*)d_in[0];   // (32,1024,1024) f32
    const float* Wt   = (const float*)d_in[1];   // (3072,1024) f32
    const float* bias = (const float*)d_in[2];   // (3072,) f32
    const int* idx    = (const int*)d_in[3];     // (32,128,6) i32
    float* out = (float*)d_out;

    // Kernel A: cp.async TF32 projection GEMM into g_qk
    {
        static bool attr_set = false;
        if (!attr_set) {
            cudaFuncSetAttribute(gemm_qk_cp,
                                 cudaFuncAttributeMaxDynamicSharedMemorySize,
                                 GEMM_SMEM);
            attr_set = true;
        }
        dim3 grid(NCOLS / 128, MROWS / 128);   // (16, 192)
        gemm_qk_cp<<<grid, 256, GEMM_SMEM>>>(TE, Wt, bias, idx);
    }

    // Kernel B: copy + zero
    {
        size_t total4 = (size_t)Bn * Sn * Hn / 4;
        copy_zero_kernel<<<(unsigned)(total4 / 256), 256>>>(TE, idx, out);
    }

    // Kernel C: attention + unified scatter (needs out already written)
    {
        static bool attr_set2 = false;
        if (!attr_set2) {
            cudaFuncSetAttribute(attn_merge_kernel,
                                 cudaFuncAttributeMaxDynamicSharedMemorySize,
                                 (int)sizeof(SmemB));
            attr_set2 = true;
        }
        attn_merge_kernel<<<Bn * Wn, 256, sizeof(SmemB)>>>(TE, idx, out);
    }
}